// round 2
// baseline (speedup 1.0000x reference)
#include <cuda_runtime.h>
#include <cuda_bf16.h>
#include <cstdint>

// Problem constants
#define BSZ   2048
#define NIN   512
#define HID   1024
#define NACT  32
#define THRESH 0.8f
#define DECAY  0.2f
#define LOG_SIG_MIN (-20.0f)
#define LOG_SIG_MAX (2.0f)

// ---------------- scratch (device globals, no allocation) ----------------
__device__ float g_I [10240 * 3072];   // I[(b*5+f)*3072 + j*1024 + h]
__device__ float g_x [BSZ * 4096];     // x[b*4096 + h*4 + k]
__device__ float g_h1a[BSZ * HID];
__device__ float g_h1b[BSZ * HID];
__device__ float g_h2a[BSZ * HID];
__device__ float g_h2b[BSZ * HID];

// ---------------- fp32 NT GEMM: C = A[M,K] * W[N,K]^T + bias, opt. ReLU --
// BM=BN=128, BK=8, 256 threads, 8x8 per thread. M%128==0, N%128==0, K%8==0.
__global__ __launch_bounds__(256)
void sgemm_nt(const float* __restrict__ A, int lda,
              const float* __restrict__ W, int ldw,
              const float* __restrict__ bias,
              float* __restrict__ C, int ldc,
              int K, int relu)
{
    __shared__ float As[8][128];
    __shared__ float Ws[8][128];

    const int tid  = threadIdx.x;
    const int bm   = blockIdx.y * 128;
    const int bn   = blockIdx.x * 128;
    const int lrow = tid >> 1;          // 0..127
    const int lcol = (tid & 1) * 4;     // 0 or 4
    const int tx   = tid & 15;          // 0..15 -> N
    const int ty   = tid >> 4;          // 0..15 -> M

    const float* Ap = A + (size_t)(bm + lrow) * lda + lcol;
    const float* Wp = W + (size_t)(bn + lrow) * ldw + lcol;

    float acc[8][8];
#pragma unroll
    for (int i = 0; i < 8; i++)
#pragma unroll
        for (int j = 0; j < 8; j++) acc[i][j] = 0.0f;

    for (int k0 = 0; k0 < K; k0 += 8) {
        float4 av = *(const float4*)(Ap + k0);
        float4 wv = *(const float4*)(Wp + k0);
        As[lcol + 0][lrow] = av.x; As[lcol + 1][lrow] = av.y;
        As[lcol + 2][lrow] = av.z; As[lcol + 3][lrow] = av.w;
        Ws[lcol + 0][lrow] = wv.x; Ws[lcol + 1][lrow] = wv.y;
        Ws[lcol + 2][lrow] = wv.z; Ws[lcol + 3][lrow] = wv.w;
        __syncthreads();

#pragma unroll
        for (int k = 0; k < 8; k++) {
            float ra[8], rb[8];
#pragma unroll
            for (int i = 0; i < 8; i++) ra[i] = As[k][ty * 8 + i];
#pragma unroll
            for (int j = 0; j < 8; j++) rb[j] = Ws[k][tx * 8 + j];
#pragma unroll
            for (int i = 0; i < 8; i++)
#pragma unroll
                for (int j = 0; j < 8; j++)
                    acc[i][j] += ra[i] * rb[j];
        }
        __syncthreads();
    }

    // epilogue: bias (+ ReLU), vectorized stores
    const int coln = bn + tx * 8;
    float4 bv0 = *(const float4*)(bias + coln);
    float4 bv1 = *(const float4*)(bias + coln + 4);
#pragma unroll
    for (int i = 0; i < 8; i++) {
        const int row = bm + ty * 8 + i;
        float v[8];
        v[0] = acc[i][0] + bv0.x; v[1] = acc[i][1] + bv0.y;
        v[2] = acc[i][2] + bv0.z; v[3] = acc[i][3] + bv0.w;
        v[4] = acc[i][4] + bv1.x; v[5] = acc[i][5] + bv1.y;
        v[6] = acc[i][6] + bv1.z; v[7] = acc[i][7] + bv1.w;
        if (relu) {
#pragma unroll
            for (int j = 0; j < 8; j++) v[j] = fmaxf(v[j], 0.0f);
        }
        float* cp = C + (size_t)row * ldc + coln;
        *(float4*)(cp)     = make_float4(v[0], v[1], v[2], v[3]);
        *(float4*)(cp + 4) = make_float4(v[4], v[5], v[6], v[7]);
    }
}

// ---------------- spiking recurrence (15 steps) + temporal mean ----------
__global__ __launch_bounds__(256)
void snn_kernel(const float* __restrict__ I,
                const float* __restrict__ wl,  // [1,3]
                const float* __restrict__ bl,  // [1]
                float* __restrict__ x)
{
    int idx = blockIdx.x * blockDim.x + threadIdx.x;   // b*1024 + h
    if (idx >= BSZ * HID) return;
    const int b = idx >> 10;
    const int h = idx & 1023;

    const float wl0 = wl[0], wl1 = wl[1], wl2 = wl[2], blv = bl[0];

    float m0 = 0.f, m1 = 0.f, m2 = 0.f, m3 = 0.f;
    float s0 = 0.f, s1 = 0.f, s2 = 0.f, s3 = 0.f;
    float a0 = 0.f, a1 = 0.f, a2 = 0.f, a3 = 0.f;

#pragma unroll
    for (int f = 0; f < 5; f++) {
        size_t base = (size_t)(b * 5 + f) * 3072 + h;
        float i1 = I[base];
        float i2 = I[base + 1024];
        float i3 = I[base + 2048];
#pragma unroll
        for (int r = 0; r < 3; r++) {
            // 'inner' uses pre-update membrane state
            float inner = m0 * wl0 + m1 * wl1 + m2 * wl2 + blv;
            m0 = m0 * DECAY * (1.0f - s0) + i1;
            m1 = m1 * DECAY * (1.0f - s1) + i2;
            m2 = m2 * DECAY * (1.0f - s2) + i3;
            m3 = m3 * DECAY * (1.0f - s3) + inner;
            s0 = (m0 > THRESH) ? 1.0f : 0.0f;
            s1 = (m1 > THRESH) ? 1.0f : 0.0f;
            s2 = (m2 > THRESH) ? 1.0f : 0.0f;
            s3 = (m3 > THRESH) ? 1.0f : 0.0f;
            a0 += s0; a1 += s1; a2 += s2; a3 += s3;
        }
    }
    const float inv = 1.0f / 15.0f;
    size_t o = (size_t)b * 4096 + (size_t)h * 4;
    x[o + 0] = a0 * inv;
    x[o + 1] = a1 * inv;
    x[o + 2] = a2 * inv;
    x[o + 3] = a3 * inv;
}

// ---------------- final heads: mean / clipped log_std -------------------
// One block per 4 batch rows; 256 threads = 4 rows x 64 outputs.
__global__ __launch_bounds__(256)
void head_kernel(const float* __restrict__ h2a,
                 const float* __restrict__ h2b,
                 const float* __restrict__ wm, const float* __restrict__ bm,
                 const float* __restrict__ ws, const float* __restrict__ bs,
                 float* __restrict__ out)
{
    __shared__ float sa[4][HID];
    __shared__ float sb[4][HID];
    const int b0  = blockIdx.x * 4;
    const int tid = threadIdx.x;

    for (int i = tid; i < 4 * HID; i += 256) {
        int r = i >> 10, k = i & 1023;
        sa[r][k] = h2a[(size_t)(b0 + r) * HID + k];
        sb[r][k] = h2b[(size_t)(b0 + r) * HID + k];
    }
    __syncthreads();

    const int r = tid >> 6;     // 0..3 (row)
    const int o = tid & 63;     // 0..63 (0..31 mean, 32..63 log_std)
    const bool is_mean = (o < 32);
    const int  n = is_mean ? o : (o - 32);
    const float* w = is_mean ? (wm + (size_t)n * HID) : (ws + (size_t)n * HID);
    const float* s = is_mean ? sa[r] : sb[r];

    float acc = 0.0f;
#pragma unroll 4
    for (int k = 0; k < HID; k += 4) {
        float4 wv = *(const float4*)(w + k);
        acc += s[k] * wv.x + s[k + 1] * wv.y + s[k + 2] * wv.z + s[k + 3] * wv.w;
    }

    const int bb = b0 + r;
    if (is_mean) {
        out[(size_t)bb * NACT + n] = acc + bm[n];
    } else {
        float v = acc + bs[n];
        v = fminf(fmaxf(v, LOG_SIG_MIN), LOG_SIG_MAX);
        out[(size_t)BSZ * NACT + (size_t)bb * NACT + n] = v;
    }
}

// ---------------- launch ---------------------------------------------------
extern "C" void kernel_launch(void* const* d_in, const int* in_sizes, int n_in,
                              void* d_out, int out_size)
{
    const float* state = (const float*)d_in[0];
    const float* w1  = (const float*)d_in[1];
    const float* b1  = (const float*)d_in[2];
    const float* w2  = (const float*)d_in[3];
    const float* b2  = (const float*)d_in[4];
    const float* w3  = (const float*)d_in[5];
    const float* b3  = (const float*)d_in[6];
    const float* wl  = (const float*)d_in[7];
    const float* bl  = (const float*)d_in[8];
    const float* w11 = (const float*)d_in[9];
    const float* b11 = (const float*)d_in[10];
    const float* w12 = (const float*)d_in[11];
    const float* b12 = (const float*)d_in[12];
    const float* w21 = (const float*)d_in[13];
    const float* b21 = (const float*)d_in[14];
    const float* w22 = (const float*)d_in[15];
    const float* b22 = (const float*)d_in[16];
    const float* wm  = (const float*)d_in[17];
    const float* bm  = (const float*)d_in[18];
    const float* ws  = (const float*)d_in[19];
    const float* bs  = (const float*)d_in[20];
    float* out = (float*)d_out;

    float *I, *x, *h1a, *h1b, *h2a, *h2b;
    cudaGetSymbolAddress((void**)&I,   g_I);
    cudaGetSymbolAddress((void**)&x,   g_x);
    cudaGetSymbolAddress((void**)&h1a, g_h1a);
    cudaGetSymbolAddress((void**)&h1b, g_h1b);
    cudaGetSymbolAddress((void**)&h2a, g_h2a);
    cudaGetSymbolAddress((void**)&h2b, g_h2b);

    // 1) Input GEMMs: I[:, j*1024 : (j+1)*1024] = state_flat @ wj^T + bj
    //    state_flat: [10240, 512]
    {
        dim3 grid(1024 / 128, 10240 / 128);
        sgemm_nt<<<grid, 256>>>(state, NIN, w1, NIN, b1, I + 0,    3072, NIN, 0);
        sgemm_nt<<<grid, 256>>>(state, NIN, w2, NIN, b2, I + 1024, 3072, NIN, 0);
        sgemm_nt<<<grid, 256>>>(state, NIN, w3, NIN, b3, I + 2048, 3072, NIN, 0);
    }

    // 2) Spiking recurrence + temporal mean -> x [B, 4096]
    snn_kernel<<<(BSZ * HID + 255) / 256, 256>>>(I, wl, bl, x);

    // 3) Head layer 1 (both branches): relu(x @ w^T + b), K=4096
    {
        dim3 grid(HID / 128, BSZ / 128);
        sgemm_nt<<<grid, 256>>>(x, 4096, w11, 4096, b11, h1a, HID, 4096, 1);
        sgemm_nt<<<grid, 256>>>(x, 4096, w21, 4096, b21, h1b, HID, 4096, 1);
        // 4) Head layer 2: K=1024
        sgemm_nt<<<grid, 256>>>(h1a, HID, w12, HID, b12, h2a, HID, HID, 1);
        sgemm_nt<<<grid, 256>>>(h1b, HID, w22, HID, b22, h2b, HID, HID, 1);
    }

    // 5) Final projections + clip -> out = [mean (B*32) | log_std (B*32)]
    head_kernel<<<BSZ / 4, 256>>>(h2a, h2b, wm, bm, ws, bs, out);
}